// round 15
// baseline (speedup 1.0000x reference)
#include <cuda_runtime.h>
#include <math.h>

#define Bv 32
#define Lv 1024
#define Dv 1536
#define Cv 256
#define Fv 64
#define Sv 101
#define NEGV -1e4f

// ---------------- scratch (device globals; allocation-free) ----------------
__device__ float g_pos[Dv * Lv];            // [k][l]
__device__ float g_y1[Bv * Lv * Cv];        // bottleneck pre-LN
__device__ float g_x1[Bv * Lv * Cv];        // post LN+relu
__device__ float g_x2[Bv * Lv * Fv];        // conv1 out
__device__ float g_gpre[2 * Lv * Bv * 512]; // lstm input projections (dir,l,b,512)
__device__ float g_WhhT[2 * 128 * 512];     // transposed recurrent weights [dir][k][r]
__device__ float g_biasc[2 * 512];
__device__ float g_hcat[Bv * Lv * 256];     // bilstm output
__device__ float g_feats[Bv * Lv * 128];    // conv2 out
__device__ float g_emis2[Bv * Lv * 2];      // 2-label emissions
__device__ float g_T[Sv * Sv];
__device__ float g_expT[Sv * Sv];
__device__ float g_start[Sv];
__device__ float g_end[Sv];
__device__ float g_alphas[Lv * Bv * Sv];    // [l][b][s]
__device__ float g_betas[Lv * Bv * Sv];
__device__ float g_logZ[Bv];
__device__ float g_best[Bv];
__device__ unsigned char g_ptr[Bv * (Lv - 1) * Sv];  // viterbi backpointers

// ---------------- block reductions (exactly 128 threads) ----------------
__device__ __forceinline__ float blkMax128(float v, float* red) {
    #pragma unroll
    for (int o = 16; o; o >>= 1) v = fmaxf(v, __shfl_xor_sync(0xffffffffu, v, o));
    if ((threadIdx.x & 31) == 0) red[threadIdx.x >> 5] = v;
    __syncthreads();
    v = fmaxf(fmaxf(red[0], red[1]), fmaxf(red[2], red[3]));
    __syncthreads();
    return v;
}
__device__ __forceinline__ float blkSum128(float v, float* red) {
    #pragma unroll
    for (int o = 16; o; o >>= 1) v += __shfl_xor_sync(0xffffffffu, v, o);
    if ((threadIdx.x & 31) == 0) red[threadIdx.x >> 5] = v;
    __syncthreads();
    v = (red[0] + red[1]) + (red[2] + red[3]);
    __syncthreads();
    return v;
}

// ---------------- positional encoding ----------------
__global__ void k_pos() {
    int k = blockIdx.x;
    float div = expf(-(float)(2 * (k >> 1)) * (9.210340371976184f / (float)Dv));
    bool is_sin = (k & 1) == 0;
    for (int l = threadIdx.x; l < Lv; l += blockDim.x) {
        float ang = (float)l * div;
        g_pos[k * Lv + l] = is_sin ? sinf(ang) : cosf(ang);
    }
}

// ---------------- CRF tables + LSTM weight transpose ----------------
__global__ void k_setup(const float* __restrict__ trans, const float* __restrict__ start,
                        const float* __restrict__ endv,
                        const float* __restrict__ Whh_f, const float* __restrict__ Whh_b,
                        const float* __restrict__ bih_f, const float* __restrict__ bhh_f,
                        const float* __restrict__ bih_b, const float* __restrict__ bhh_b) {
    int gs = blockIdx.x * blockDim.x + threadIdx.x;
    int stride = gridDim.x * blockDim.x;
    for (int idx = gs; idx < Sv * Sv; idx += stride) {
        int i = idx / Sv, j = idx % Sv;
        bool allow = (i == 0 && j <= 1) || (i >= 1 && i <= 98 && j == i + 1) ||
                     (i >= 4 && i <= 99 && j == 100) || (i == 99 && j == 99) ||
                     (i == 100 && j <= 1);
        float t = allow ? trans[idx] : NEGV;
        g_T[idx] = t;
        g_expT[idx] = expf(t);
    }
    for (int idx = gs; idx < Sv; idx += stride) {
        g_start[idx] = start[idx];
        g_end[idx] = (idx == 0 || idx == 100) ? endv[idx] : NEGV;
    }
    for (int idx = gs; idx < 2 * 128 * 512; idx += stride) {
        int dir = idx >> 16, rem = idx & 65535;
        int k = rem >> 9, r = rem & 511;
        const float* w = dir ? Whh_b : Whh_f;
        g_WhhT[idx] = w[r * 128 + k];
    }
    for (int idx = gs; idx < 1024; idx += stride) {
        int dir = idx >> 9, r = idx & 511;
        g_biasc[idx] = dir ? (bih_b[r] + bhh_b[r]) : (bih_f[r] + bhh_f[r]);
    }
}

// ---------------- GEMM 1: bottleneck (M=32768,K=1536,N=256), A = emb^T + pos ----------------
__global__ void k_gemm1(const float* __restrict__ emb, const float* __restrict__ W,
                        const float* __restrict__ bias) {
    __shared__ float As[16][68];
    __shared__ float Bs[16][68];
    int m0 = blockIdx.x * 64, n0 = blockIdx.y * 64;
    int tid = threadIdx.x;
    int tx = tid & 15, ty = tid >> 4;
    int b = m0 >> 10, l0 = m0 & 1023;
    float acc[4][4] = {};
    for (int k0 = 0; k0 < Dv; k0 += 16) {
        #pragma unroll
        for (int r = 0; r < 4; r++) {
            int idx = tid + r * 256;
            int kk = idx >> 6, mm = idx & 63;
            int k = k0 + kk, l = l0 + mm;
            As[kk][mm] = emb[(b * Dv + k) * Lv + l] + g_pos[k * Lv + l];
            Bs[kk][mm] = W[k * Cv + n0 + mm];
        }
        __syncthreads();
        #pragma unroll
        for (int kk = 0; kk < 16; kk++) {
            float4 a4 = *(const float4*)&As[kk][ty * 4];
            float4 b4 = *(const float4*)&Bs[kk][tx * 4];
            float av[4] = {a4.x, a4.y, a4.z, a4.w};
            float bv[4] = {b4.x, b4.y, b4.z, b4.w};
            #pragma unroll
            for (int i = 0; i < 4; i++)
                #pragma unroll
                for (int j = 0; j < 4; j++) acc[i][j] += av[i] * bv[j];
        }
        __syncthreads();
    }
    #pragma unroll
    for (int i = 0; i < 4; i++) {
        int m = m0 + ty * 4 + i;
        #pragma unroll
        for (int j = 0; j < 4; j++) {
            int n = n0 + tx * 4 + j;
            g_y1[m * Cv + n] = acc[i][j] + bias[n];
        }
    }
}

// ---------------- LayerNorm + ReLU over rows of 256 ----------------
__global__ void k_ln(const float* __restrict__ g, const float* __restrict__ bt) {
    __shared__ float red[4];
    int r = blockIdx.x, tid = threadIdx.x;
    const float* x = g_y1 + r * Cv;
    float v0 = x[tid], v1 = x[tid + 128];
    float s = blkSum128(v0 + v1, red);
    float mean = s * (1.0f / Cv);
    float d0 = v0 - mean, d1 = v1 - mean;
    float sq = blkSum128(d0 * d0 + d1 * d1, red);
    float inv = rsqrtf(sq * (1.0f / Cv) + 1e-5f);
    float* o = g_x1 + r * Cv;
    o[tid] = fmaxf(d0 * inv * g[tid] + bt[tid], 0.f);
    o[tid + 128] = fmaxf(d1 * inv * g[tid + 128] + bt[tid + 128], 0.f);
}

// ---------------- conv1 as GEMM (M=32768,N=64,K=768), k = d*256 + c ----------------
__global__ void k_conv1(const float* __restrict__ w, const float* __restrict__ bias) {
    __shared__ float As[16][68];
    __shared__ float Bs[16][68];
    int m0 = blockIdx.x * 64;
    int tid = threadIdx.x;
    int tx = tid & 15, ty = tid >> 4;
    int b = m0 >> 10, l0 = m0 & 1023;
    float acc[4][4] = {};
    for (int k0 = 0; k0 < 768; k0 += 16) {
        #pragma unroll
        for (int r = 0; r < 4; r++) {
            int idx = tid + r * 256;
            int kk = idx & 15, mm = idx >> 4;
            int k = k0 + kk;
            int d = k / 256, c = k & 255;
            int l2 = l0 + mm + d - 1;
            As[kk][mm] = ((unsigned)l2 < (unsigned)Lv) ? g_x1[((b << 10) + l2) * Cv + c] : 0.f;
            Bs[kk][mm] = w[mm * 768 + c * 3 + d];
        }
        __syncthreads();
        #pragma unroll
        for (int kk = 0; kk < 16; kk++) {
            float4 a4 = *(const float4*)&As[kk][ty * 4];
            float4 b4 = *(const float4*)&Bs[kk][tx * 4];
            float av[4] = {a4.x, a4.y, a4.z, a4.w};
            float bv[4] = {b4.x, b4.y, b4.z, b4.w};
            #pragma unroll
            for (int i = 0; i < 4; i++)
                #pragma unroll
                for (int j = 0; j < 4; j++) acc[i][j] += av[i] * bv[j];
        }
        __syncthreads();
    }
    #pragma unroll
    for (int i = 0; i < 4; i++) {
        int m = m0 + ty * 4 + i;
        #pragma unroll
        for (int j = 0; j < 4; j++) {
            int n = tx * 4 + j;
            g_x2[m * Fv + n] = fmaxf(acc[i][j] + bias[n], 0.f);
        }
    }
}

// ---------------- x projections for both LSTM dirs (M=32768,N=512,K=64) ----------------
__global__ void k_xproj(const float* __restrict__ Wih_f, const float* __restrict__ Wih_b) {
    __shared__ float As[16][68];
    __shared__ float Bs[16][68];
    int m0 = blockIdx.x * 64, n0 = blockIdx.y * 64;
    int dir = blockIdx.z;
    const float* Wih = dir ? Wih_b : Wih_f;
    int tid = threadIdx.x;
    int tx = tid & 15, ty = tid >> 4;
    float acc[4][4] = {};
    for (int k0 = 0; k0 < 64; k0 += 16) {
        #pragma unroll
        for (int r = 0; r < 4; r++) {
            int idx = tid + r * 256;
            int kk = idx & 15, mm = idx >> 4;
            As[kk][mm] = g_x2[(m0 + mm) * Fv + k0 + kk];
            Bs[kk][mm] = Wih[(n0 + mm) * 64 + k0 + kk];
        }
        __syncthreads();
        #pragma unroll
        for (int kk = 0; kk < 16; kk++) {
            float4 a4 = *(const float4*)&As[kk][ty * 4];
            float4 b4 = *(const float4*)&Bs[kk][tx * 4];
            float av[4] = {a4.x, a4.y, a4.z, a4.w};
            float bv[4] = {b4.x, b4.y, b4.z, b4.w};
            #pragma unroll
            for (int i = 0; i < 4; i++)
                #pragma unroll
                for (int j = 0; j < 4; j++) acc[i][j] += av[i] * bv[j];
        }
        __syncthreads();
    }
    #pragma unroll
    for (int i = 0; i < 4; i++) {
        int m = m0 + ty * 4 + i;
        int b = m >> 10, l = m & 1023;
        #pragma unroll
        for (int j = 0; j < 4; j++) {
            int n = n0 + tx * 4 + j;
            g_gpre[((dir * Lv + l) * Bv + b) * 512 + n] = acc[i][j] + g_biasc[dir * 512 + n];
        }
    }
}

// ---------------- persistent BiLSTM: 32 blocks = (dir, batch-pair) ----------------
__global__ void k_lstm() {
    __shared__ float2 h2[128];     // hidden for {batch0, batch1}
    __shared__ float gsh[2][512];  // gates per batch
    int bid = blockIdx.x;
    int dir = bid >> 4;
    int bp = (bid & 15) * 2;
    int tid = threadIdx.x;  // 256
    if (tid < 128) h2[tid] = make_float2(0.f, 0.f);
    float c = 0.f;
    int bb = tid >> 7, j = tid & 127;  // gate-activation role
    __syncthreads();
    const float* WT = g_WhhT + dir * 65536;
    for (int t = 0; t < Lv; t++) {
        int l = dir ? (Lv - 1 - t) : t;
        int r0 = tid * 2;
        float a00 = 0.f, a01 = 0.f, a10 = 0.f, a11 = 0.f;
        #pragma unroll 8
        for (int k = 0; k < 128; k++) {
            float2 w = *(const float2*)(WT + k * 512 + r0);
            float2 h = h2[k];
            a00 += w.x * h.x; a01 += w.x * h.y;
            a10 += w.y * h.x; a11 += w.y * h.y;
        }
        const float* pre = g_gpre + ((dir * Lv + l) * Bv) * 512;
        float2 p0 = *(const float2*)(pre + bp * 512 + r0);
        float2 p1 = *(const float2*)(pre + (bp + 1) * 512 + r0);
        gsh[0][r0] = a00 + p0.x; gsh[0][r0 + 1] = a10 + p0.y;
        gsh[1][r0] = a01 + p1.x; gsh[1][r0 + 1] = a11 + p1.y;
        __syncthreads();
        {
            float gi = gsh[bb][j], gf = gsh[bb][128 + j];
            float gg = gsh[bb][256 + j], go = gsh[bb][384 + j];
            float i_ = 1.f / (1.f + expf(-gi));
            float f_ = 1.f / (1.f + expf(-gf));
            float g_ = tanhf(gg);
            float o_ = 1.f / (1.f + expf(-go));
            c = f_ * c + i_ * g_;
            float hn = o_ * tanhf(c);
            if (bb == 0) h2[j].x = hn; else h2[j].y = hn;
            g_hcat[((bp + bb) * Lv + l) * 256 + dir * 128 + j] = hn;
        }
        __syncthreads();
    }
}

// ---------------- conv2 as GEMM (M=32768,N=128,K=1280), k = d*256 + c ----------------
__global__ void k_conv2(const float* __restrict__ w, const float* __restrict__ bias) {
    __shared__ float As[16][68];
    __shared__ float Bs[16][68];
    int m0 = blockIdx.x * 64, n0 = blockIdx.y * 64;
    int tid = threadIdx.x;
    int tx = tid & 15, ty = tid >> 4;
    int b = m0 >> 10, l0 = m0 & 1023;
    float acc[4][4] = {};
    for (int k0 = 0; k0 < 1280; k0 += 16) {
        #pragma unroll
        for (int r = 0; r < 4; r++) {
            int idx = tid + r * 256;
            int kk = idx & 15, mm = idx >> 4;
            int k = k0 + kk;
            int d = k / 256, c = k & 255;
            int l2 = l0 + mm + d - 2;
            As[kk][mm] = ((unsigned)l2 < (unsigned)Lv) ? g_hcat[((b << 10) + l2) * 256 + c] : 0.f;
            Bs[kk][mm] = w[(n0 + mm) * 1280 + c * 5 + d];
        }
        __syncthreads();
        #pragma unroll
        for (int kk = 0; kk < 16; kk++) {
            float4 a4 = *(const float4*)&As[kk][ty * 4];
            float4 b4 = *(const float4*)&Bs[kk][tx * 4];
            float av[4] = {a4.x, a4.y, a4.z, a4.w};
            float bv[4] = {b4.x, b4.y, b4.z, b4.w};
            #pragma unroll
            for (int i = 0; i < 4; i++)
                #pragma unroll
                for (int j = 0; j < 4; j++) acc[i][j] += av[i] * bv[j];
        }
        __syncthreads();
    }
    #pragma unroll
    for (int i = 0; i < 4; i++) {
        int m = m0 + ty * 4 + i;
        #pragma unroll
        for (int j = 0; j < 4; j++) {
            int n = n0 + tx * 4 + j;
            g_feats[m * 128 + n] = fmaxf(acc[i][j] + bias[n], 0.f);
        }
    }
}

// ---------------- emissions (2 labels) ----------------
__global__ void k_emis(const float* __restrict__ W, const float* __restrict__ bb) {
    __shared__ float red[4];
    int m = blockIdx.x;
    int tid = threadIdx.x;
    float f = g_feats[m * 128 + tid];
    float s0 = blkSum128(f * W[tid * 2], red);
    float s1 = blkSum128(f * W[tid * 2 + 1], red);
    if (tid == 0) {
        g_emis2[m * 2] = s0 + bb[0];
        g_emis2[m * 2 + 1] = s1 + bb[1];
    }
}

// ---------------- fused CRF: 96 blocks, role = fwd / bwd / viterbi ----------------
__global__ void k_crf(float* out, int out_size) {
    __shared__ float sT[Sv * Sv];
    __shared__ float aA[104];
    __shared__ float aB[104];
    __shared__ float red[4];
    int role = blockIdx.x >> 5;
    int b = blockIdx.x & 31;
    int tid = threadIdx.x;  // 128
    const float* src = (role == 2) ? g_T : g_expT;
    for (int i = tid; i < Sv * Sv; i += 128) sT[i] = src[i];
    if (tid < 104) { aA[tid] = -INFINITY; aB[tid] = -INFINITY; }
    __syncthreads();
    const float* E = g_emis2 + b * 2048;

    if (role == 0) {
        // ---- forward ----
        if (tid < Sv) {
            float a0 = g_start[tid] + (tid == 0 ? E[0] : E[1]);
            aA[tid] = a0;
            g_alphas[b * Sv + tid] = a0;
        }
        __syncthreads();
        for (int t = 1; t < Lv; t++) {
            float v = (tid < Sv) ? aA[tid] : -INFINITY;
            float m = blkMax128(v, red);
            if (tid < Sv) aB[tid] = __expf(aA[tid] - m);
            __syncthreads();
            float e0 = E[t * 2], e1 = E[t * 2 + 1];
            float anew = -INFINITY;
            if (tid < Sv) {
                float s = 0.f;
                #pragma unroll 4
                for (int i = 0; i < Sv; i++) s += aB[i] * sT[i * Sv + tid];
                anew = m + logf(s) + (tid == 0 ? e0 : e1);
                g_alphas[(t * Bv + b) * Sv + tid] = anew;
            }
            __syncthreads();
            if (tid < Sv) aA[tid] = anew;
            __syncthreads();
        }
        float v = (tid < Sv) ? aA[tid] + g_end[tid] : -INFINITY;
        float m = blkMax128(v, red);
        float s = blkSum128((tid < Sv) ? __expf(v - m) : 0.f, red);
        if (tid == 0) g_logZ[b] = m + logf(s);
    } else if (role == 1) {
        // ---- backward ----
        if (tid < Sv) {
            aA[tid] = g_end[tid];
            g_betas[(1023 * Bv + b) * Sv + tid] = aA[tid];
        }
        __syncthreads();
        for (int t = Lv - 2; t >= 0; t--) {
            float e0 = E[(t + 1) * 2], e1 = E[(t + 1) * 2 + 1];
            float q = (tid < Sv) ? aA[tid] + (tid == 0 ? e0 : e1) : -INFINITY;
            float m = blkMax128(q, red);
            if (tid < Sv) aB[tid] = __expf(q - m);
            __syncthreads();
            float bnew = -INFINITY;
            if (tid < Sv) {
                float s = 0.f;
                #pragma unroll 4
                for (int j = 0; j < Sv; j++) s += sT[tid * Sv + j] * aB[j];
                bnew = m + logf(s);
                g_betas[(t * Bv + b) * Sv + tid] = bnew;
            }
            __syncthreads();
            if (tid < Sv) aA[tid] = bnew;
            __syncthreads();
        }
    } else {
        // ---- viterbi ----
        if (tid < Sv) aA[tid] = g_start[tid] + (tid == 0 ? E[0] : E[1]);
        __syncthreads();
        float* cur = aA;
        float* nxt = aB;
        unsigned char* P = g_ptr + b * (Lv - 1) * Sv;
        for (int t = 1; t < Lv; t++) {
            float e0 = E[t * 2], e1 = E[t * 2 + 1];
            if (tid < Sv) {
                float best = -INFINITY;
                int bi = 0;
                #pragma unroll 4
                for (int i = 0; i < Sv; i++) {
                    float sc = cur[i] + sT[i * Sv + tid];
                    if (sc > best) { best = sc; bi = i; }
                }
                nxt[tid] = best + (tid == 0 ? e0 : e1);
                P[(t - 1) * Sv + tid] = (unsigned char)bi;
            }
            __syncthreads();
            float* tmp = cur; cur = nxt; nxt = tmp;
        }
        if (tid == 0 && out_size >= Bv * Lv * Sv + Bv * Lv) {
            float best = -INFINITY;
            int last = 0;
            for (int j = 0; j < Sv; j++) {
                float f = cur[j] + g_end[j];
                if (f > best) { best = f; last = j; }
            }
            g_best[b] = best;
            float* paths = out + Bv * Lv * Sv;
            int st = last;
            paths[b * Lv + Lv - 1] = (float)st;
            for (int t = Lv - 1; t >= 1; t--) {
                st = P[(t - 1) * Sv + st];
                paths[b * Lv + t - 1] = (float)st;
            }
        }
    }
}

// ---------------- marginals + path probs ----------------
__global__ void k_marg(float* out, int out_size) {
    __shared__ float red[4];
    int bl = blockIdx.x;  // = b*1024 + l
    int b = bl >> 10, l = bl & 1023;
    int tid = threadIdx.x;
    int base = (l * Bv + b) * Sv;
    float v = (tid < Sv) ? g_alphas[base + tid] + g_betas[base + tid] : -INFINITY;
    float m = blkMax128(v, red);
    float e = (tid < Sv) ? __expf(v - m) : 0.f;
    float s = blkSum128(e, red);
    if (tid < Sv) out[bl * Sv + tid] = e / s;
    if (bl == 0 && tid < Bv && out_size >= Bv * Lv * Sv + Bv * Lv + Bv)
        out[Bv * Lv * Sv + Bv * Lv + tid] = __expf(g_best[tid] - g_logZ[tid]);
}

extern "C" void kernel_launch(void* const* d_in, const int* in_sizes, int n_in,
                              void* d_out, int out_size) {
    // Locate W_bneck by its unique size; weights follow in dict order.
    int iW = 3;
    for (int i = 0; i < n_in; i++)
        if (in_sizes[i] == Dv * Cv) { iW = i; break; }
    const float* emb     = (const float*)d_in[0];
    const float* W_bneck = (const float*)d_in[iW];
    const float* b_bneck = (const float*)d_in[iW + 1];
    const float* ln_g    = (const float*)d_in[iW + 2];
    const float* ln_b    = (const float*)d_in[iW + 3];
    const float* conv1_w = (const float*)d_in[iW + 4];
    const float* conv1_b = (const float*)d_in[iW + 5];
    const float* Wih_f   = (const float*)d_in[iW + 6];
    const float* Whh_f   = (const float*)d_in[iW + 7];
    const float* bih_f   = (const float*)d_in[iW + 8];
    const float* bhh_f   = (const float*)d_in[iW + 9];
    const float* Wih_b   = (const float*)d_in[iW + 10];
    const float* Whh_b   = (const float*)d_in[iW + 11];
    const float* bih_b   = (const float*)d_in[iW + 12];
    const float* bhh_b   = (const float*)d_in[iW + 13];
    const float* conv2_w = (const float*)d_in[iW + 14];
    const float* conv2_b = (const float*)d_in[iW + 15];
    const float* W_emis  = (const float*)d_in[iW + 16];
    const float* b_emis  = (const float*)d_in[iW + 17];
    const float* crf_t   = (const float*)d_in[iW + 18];
    const float* crf_s   = (const float*)d_in[iW + 19];
    const float* crf_e   = (const float*)d_in[iW + 20];
    float* out = (float*)d_out;

    k_pos<<<Dv, 128>>>();
    k_setup<<<128, 256>>>(crf_t, crf_s, crf_e, Whh_f, Whh_b, bih_f, bhh_f, bih_b, bhh_b);
    k_gemm1<<<dim3(512, 4), 256>>>(emb, W_bneck, b_bneck);
    k_ln<<<Bv * Lv, 128>>>(ln_g, ln_b);
    k_conv1<<<512, 256>>>(conv1_w, conv1_b);
    k_xproj<<<dim3(512, 8, 2), 256>>>(Wih_f, Wih_b);
    k_lstm<<<32, 256>>>();
    k_conv2<<<dim3(512, 2), 256>>>(conv2_w, conv2_b);
    k_emis<<<Bv * Lv, 128>>>(W_emis, b_emis);
    k_crf<<<96, 128>>>(out, out_size);
    k_marg<<<Bv * Lv, 128>>>(out, out_size);
}

// round 16
// speedup vs baseline: 1.0249x; 1.0249x over previous
#include <cuda_runtime.h>
#include <math.h>

#define Bv 32
#define Lv 1024
#define Dv 1536
#define Cv 256
#define Fv 64
#define Sv 101
#define NEGV -1e4f

// ---------------- scratch (device globals; allocation-free) ----------------
__device__ float g_pos[Dv * Lv];            // [k][l]
__device__ float g_y1[Bv * Lv * Cv];        // bottleneck pre-LN
__device__ float g_x1[Bv * Lv * Cv];        // post LN+relu
__device__ float g_x2[Bv * Lv * Fv];        // conv1 out
__device__ float g_gpre[2 * Lv * Bv * 512]; // lstm input projections (dir,l,b,512)
__device__ float g_WhhT[2 * 128 * 512];     // transposed recurrent weights [dir][k][r]
__device__ float g_biasc[2 * 512];
__device__ float g_hcat[Bv * Lv * 256];     // bilstm output
__device__ float g_feats[Bv * Lv * 128];    // conv2 out
__device__ float g_emis2[Bv * Lv * 2];      // 2-label emissions
__device__ float g_T[Sv * Sv];
__device__ float g_expT[Sv * Sv];
__device__ float g_start[Sv];
__device__ float g_end[Sv];
__device__ float g_alphas[Lv * Bv * Sv];    // [l][b][s]
__device__ float g_betas[Lv * Bv * Sv];
__device__ float g_logZ[Bv];
__device__ float g_best[Bv];
__device__ unsigned char g_ptr[Bv * (Lv - 1) * Sv];  // viterbi backpointers

// ---------------- block reductions (exactly 128 threads) ----------------
__device__ __forceinline__ float blkMax128(float v, float* red) {
    #pragma unroll
    for (int o = 16; o; o >>= 1) v = fmaxf(v, __shfl_xor_sync(0xffffffffu, v, o));
    if ((threadIdx.x & 31) == 0) red[threadIdx.x >> 5] = v;
    __syncthreads();
    v = fmaxf(fmaxf(red[0], red[1]), fmaxf(red[2], red[3]));
    __syncthreads();
    return v;
}
__device__ __forceinline__ float blkSum128(float v, float* red) {
    #pragma unroll
    for (int o = 16; o; o >>= 1) v += __shfl_xor_sync(0xffffffffu, v, o);
    if ((threadIdx.x & 31) == 0) red[threadIdx.x >> 5] = v;
    __syncthreads();
    v = (red[0] + red[1]) + (red[2] + red[3]);
    __syncthreads();
    return v;
}

// ---------------- positional encoding ----------------
__global__ void k_pos() {
    int k = blockIdx.x;
    float div = expf(-(float)(2 * (k >> 1)) * (9.210340371976184f / (float)Dv));
    bool is_sin = (k & 1) == 0;
    for (int l = threadIdx.x; l < Lv; l += blockDim.x) {
        float ang = (float)l * div;
        g_pos[k * Lv + l] = is_sin ? sinf(ang) : cosf(ang);
    }
}

// ---------------- CRF tables + LSTM weight transpose ----------------
__global__ void k_setup(const float* __restrict__ trans, const float* __restrict__ start,
                        const float* __restrict__ endv,
                        const float* __restrict__ Whh_f, const float* __restrict__ Whh_b,
                        const float* __restrict__ bih_f, const float* __restrict__ bhh_f,
                        const float* __restrict__ bih_b, const float* __restrict__ bhh_b) {
    int gs = blockIdx.x * blockDim.x + threadIdx.x;
    int stride = gridDim.x * blockDim.x;
    for (int idx = gs; idx < Sv * Sv; idx += stride) {
        int i = idx / Sv, j = idx % Sv;
        bool allow = (i == 0 && j <= 1) || (i >= 1 && i <= 98 && j == i + 1) ||
                     (i >= 4 && i <= 99 && j == 100) || (i == 99 && j == 99) ||
                     (i == 100 && j <= 1);
        float t = allow ? trans[idx] : NEGV;
        g_T[idx] = t;
        g_expT[idx] = expf(t);
    }
    for (int idx = gs; idx < Sv; idx += stride) {
        g_start[idx] = start[idx];
        g_end[idx] = (idx == 0 || idx == 100) ? endv[idx] : NEGV;
    }
    for (int idx = gs; idx < 2 * 128 * 512; idx += stride) {
        int dir = idx >> 16, rem = idx & 65535;
        int k = rem >> 9, r = rem & 511;
        const float* w = dir ? Whh_b : Whh_f;
        g_WhhT[idx] = w[r * 128 + k];
    }
    for (int idx = gs; idx < 1024; idx += stride) {
        int dir = idx >> 9, r = idx & 511;
        g_biasc[idx] = dir ? (bih_b[r] + bhh_b[r]) : (bih_f[r] + bhh_f[r]);
    }
}

// ---------------- GEMM 1: bottleneck (M=32768,K=1536,N=256), A = emb^T + pos ----------------
__global__ void k_gemm1(const float* __restrict__ emb, const float* __restrict__ W,
                        const float* __restrict__ bias) {
    __shared__ float As[16][68];
    __shared__ float Bs[16][68];
    int m0 = blockIdx.x * 64, n0 = blockIdx.y * 64;
    int tid = threadIdx.x;
    int tx = tid & 15, ty = tid >> 4;
    int b = m0 >> 10, l0 = m0 & 1023;
    float acc[4][4] = {};
    for (int k0 = 0; k0 < Dv; k0 += 16) {
        #pragma unroll
        for (int r = 0; r < 4; r++) {
            int idx = tid + r * 256;
            int kk = idx >> 6, mm = idx & 63;
            int k = k0 + kk, l = l0 + mm;
            As[kk][mm] = emb[(b * Dv + k) * Lv + l] + g_pos[k * Lv + l];
            Bs[kk][mm] = W[k * Cv + n0 + mm];
        }
        __syncthreads();
        #pragma unroll
        for (int kk = 0; kk < 16; kk++) {
            float4 a4 = *(const float4*)&As[kk][ty * 4];
            float4 b4 = *(const float4*)&Bs[kk][tx * 4];
            float av[4] = {a4.x, a4.y, a4.z, a4.w};
            float bv[4] = {b4.x, b4.y, b4.z, b4.w};
            #pragma unroll
            for (int i = 0; i < 4; i++)
                #pragma unroll
                for (int j = 0; j < 4; j++) acc[i][j] += av[i] * bv[j];
        }
        __syncthreads();
    }
    #pragma unroll
    for (int i = 0; i < 4; i++) {
        int m = m0 + ty * 4 + i;
        #pragma unroll
        for (int j = 0; j < 4; j++) {
            int n = n0 + tx * 4 + j;
            g_y1[m * Cv + n] = acc[i][j] + bias[n];
        }
    }
}

// ---------------- LayerNorm + ReLU over rows of 256 ----------------
__global__ void k_ln(const float* __restrict__ g, const float* __restrict__ bt) {
    __shared__ float red[4];
    int r = blockIdx.x, tid = threadIdx.x;
    const float* x = g_y1 + r * Cv;
    float v0 = x[tid], v1 = x[tid + 128];
    float s = blkSum128(v0 + v1, red);
    float mean = s * (1.0f / Cv);
    float d0 = v0 - mean, d1 = v1 - mean;
    float sq = blkSum128(d0 * d0 + d1 * d1, red);
    float inv = rsqrtf(sq * (1.0f / Cv) + 1e-5f);
    float* o = g_x1 + r * Cv;
    o[tid] = fmaxf(d0 * inv * g[tid] + bt[tid], 0.f);
    o[tid + 128] = fmaxf(d1 * inv * g[tid + 128] + bt[tid + 128], 0.f);
}

// ---------------- conv1 as GEMM (M=32768,N=64,K=768), k = d*256 + c ----------------
__global__ void k_conv1(const float* __restrict__ w, const float* __restrict__ bias) {
    __shared__ float As[16][68];
    __shared__ float Bs[16][68];
    int m0 = blockIdx.x * 64;
    int tid = threadIdx.x;
    int tx = tid & 15, ty = tid >> 4;
    int b = m0 >> 10, l0 = m0 & 1023;
    float acc[4][4] = {};
    for (int k0 = 0; k0 < 768; k0 += 16) {
        #pragma unroll
        for (int r = 0; r < 4; r++) {
            int idx = tid + r * 256;
            int kk = idx & 15, mm = idx >> 4;
            int k = k0 + kk;
            int d = k / 256, c = k & 255;
            int l2 = l0 + mm + d - 1;
            As[kk][mm] = ((unsigned)l2 < (unsigned)Lv) ? g_x1[((b << 10) + l2) * Cv + c] : 0.f;
            Bs[kk][mm] = w[mm * 768 + c * 3 + d];
        }
        __syncthreads();
        #pragma unroll
        for (int kk = 0; kk < 16; kk++) {
            float4 a4 = *(const float4*)&As[kk][ty * 4];
            float4 b4 = *(const float4*)&Bs[kk][tx * 4];
            float av[4] = {a4.x, a4.y, a4.z, a4.w};
            float bv[4] = {b4.x, b4.y, b4.z, b4.w};
            #pragma unroll
            for (int i = 0; i < 4; i++)
                #pragma unroll
                for (int j = 0; j < 4; j++) acc[i][j] += av[i] * bv[j];
        }
        __syncthreads();
    }
    #pragma unroll
    for (int i = 0; i < 4; i++) {
        int m = m0 + ty * 4 + i;
        #pragma unroll
        for (int j = 0; j < 4; j++) {
            int n = tx * 4 + j;
            g_x2[m * Fv + n] = fmaxf(acc[i][j] + bias[n], 0.f);
        }
    }
}

// ---------------- x projections for both LSTM dirs (M=32768,N=512,K=64) ----------------
__global__ void k_xproj(const float* __restrict__ Wih_f, const float* __restrict__ Wih_b) {
    __shared__ float As[16][68];
    __shared__ float Bs[16][68];
    int m0 = blockIdx.x * 64, n0 = blockIdx.y * 64;
    int dir = blockIdx.z;
    const float* Wih = dir ? Wih_b : Wih_f;
    int tid = threadIdx.x;
    int tx = tid & 15, ty = tid >> 4;
    float acc[4][4] = {};
    for (int k0 = 0; k0 < 64; k0 += 16) {
        #pragma unroll
        for (int r = 0; r < 4; r++) {
            int idx = tid + r * 256;
            int kk = idx & 15, mm = idx >> 4;
            As[kk][mm] = g_x2[(m0 + mm) * Fv + k0 + kk];
            Bs[kk][mm] = Wih[(n0 + mm) * 64 + k0 + kk];
        }
        __syncthreads();
        #pragma unroll
        for (int kk = 0; kk < 16; kk++) {
            float4 a4 = *(const float4*)&As[kk][ty * 4];
            float4 b4 = *(const float4*)&Bs[kk][tx * 4];
            float av[4] = {a4.x, a4.y, a4.z, a4.w};
            float bv[4] = {b4.x, b4.y, b4.z, b4.w};
            #pragma unroll
            for (int i = 0; i < 4; i++)
                #pragma unroll
                for (int j = 0; j < 4; j++) acc[i][j] += av[i] * bv[j];
        }
        __syncthreads();
    }
    #pragma unroll
    for (int i = 0; i < 4; i++) {
        int m = m0 + ty * 4 + i;
        int b = m >> 10, l = m & 1023;
        #pragma unroll
        for (int j = 0; j < 4; j++) {
            int n = n0 + tx * 4 + j;
            g_gpre[((dir * Lv + l) * Bv + b) * 512 + n] = acc[i][j] + g_biasc[dir * 512 + n];
        }
    }
}

// ---------------- persistent BiLSTM: 32 blocks = (dir, batch-pair) ----------------
__global__ void k_lstm() {
    __shared__ float2 h2[128];     // hidden for {batch0, batch1}
    __shared__ float gsh[2][512];  // gates per batch
    int bid = blockIdx.x;
    int dir = bid >> 4;
    int bp = (bid & 15) * 2;
    int tid = threadIdx.x;  // 256
    if (tid < 128) h2[tid] = make_float2(0.f, 0.f);
    float c = 0.f;
    int bb = tid >> 7, j = tid & 127;  // gate-activation role
    __syncthreads();
    const float* WT = g_WhhT + dir * 65536;
    for (int t = 0; t < Lv; t++) {
        int l = dir ? (Lv - 1 - t) : t;
        int r0 = tid * 2;
        float a00 = 0.f, a01 = 0.f, a10 = 0.f, a11 = 0.f;
        #pragma unroll 8
        for (int k = 0; k < 128; k++) {
            float2 w = *(const float2*)(WT + k * 512 + r0);
            float2 h = h2[k];
            a00 += w.x * h.x; a01 += w.x * h.y;
            a10 += w.y * h.x; a11 += w.y * h.y;
        }
        const float* pre = g_gpre + ((dir * Lv + l) * Bv) * 512;
        float2 p0 = *(const float2*)(pre + bp * 512 + r0);
        float2 p1 = *(const float2*)(pre + (bp + 1) * 512 + r0);
        gsh[0][r0] = a00 + p0.x; gsh[0][r0 + 1] = a10 + p0.y;
        gsh[1][r0] = a01 + p1.x; gsh[1][r0 + 1] = a11 + p1.y;
        __syncthreads();
        {
            float gi = gsh[bb][j], gf = gsh[bb][128 + j];
            float gg = gsh[bb][256 + j], go = gsh[bb][384 + j];
            float i_ = 1.f / (1.f + expf(-gi));
            float f_ = 1.f / (1.f + expf(-gf));
            float g_ = tanhf(gg);
            float o_ = 1.f / (1.f + expf(-go));
            c = f_ * c + i_ * g_;
            float hn = o_ * tanhf(c);
            if (bb == 0) h2[j].x = hn; else h2[j].y = hn;
            g_hcat[((bp + bb) * Lv + l) * 256 + dir * 128 + j] = hn;
        }
        __syncthreads();
    }
}

// ---------------- conv2 as GEMM (M=32768,N=128,K=1280), k = d*256 + c ----------------
__global__ void k_conv2(const float* __restrict__ w, const float* __restrict__ bias) {
    __shared__ float As[16][68];
    __shared__ float Bs[16][68];
    int m0 = blockIdx.x * 64, n0 = blockIdx.y * 64;
    int tid = threadIdx.x;
    int tx = tid & 15, ty = tid >> 4;
    int b = m0 >> 10, l0 = m0 & 1023;
    float acc[4][4] = {};
    for (int k0 = 0; k0 < 1280; k0 += 16) {
        #pragma unroll
        for (int r = 0; r < 4; r++) {
            int idx = tid + r * 256;
            int kk = idx & 15, mm = idx >> 4;
            int k = k0 + kk;
            int d = k / 256, c = k & 255;
            int l2 = l0 + mm + d - 2;
            As[kk][mm] = ((unsigned)l2 < (unsigned)Lv) ? g_hcat[((b << 10) + l2) * 256 + c] : 0.f;
            Bs[kk][mm] = w[(n0 + mm) * 1280 + c * 5 + d];
        }
        __syncthreads();
        #pragma unroll
        for (int kk = 0; kk < 16; kk++) {
            float4 a4 = *(const float4*)&As[kk][ty * 4];
            float4 b4 = *(const float4*)&Bs[kk][tx * 4];
            float av[4] = {a4.x, a4.y, a4.z, a4.w};
            float bv[4] = {b4.x, b4.y, b4.z, b4.w};
            #pragma unroll
            for (int i = 0; i < 4; i++)
                #pragma unroll
                for (int j = 0; j < 4; j++) acc[i][j] += av[i] * bv[j];
        }
        __syncthreads();
    }
    #pragma unroll
    for (int i = 0; i < 4; i++) {
        int m = m0 + ty * 4 + i;
        #pragma unroll
        for (int j = 0; j < 4; j++) {
            int n = n0 + tx * 4 + j;
            g_feats[m * 128 + n] = fmaxf(acc[i][j] + bias[n], 0.f);
        }
    }
}

// ---------------- emissions (2 labels) ----------------
__global__ void k_emis(const float* __restrict__ W, const float* __restrict__ bb) {
    __shared__ float red[4];
    int m = blockIdx.x;
    int tid = threadIdx.x;
    float f = g_feats[m * 128 + tid];
    float s0 = blkSum128(f * W[tid * 2], red);
    float s1 = blkSum128(f * W[tid * 2 + 1], red);
    if (tid == 0) {
        g_emis2[m * 2] = s0 + bb[0];
        g_emis2[m * 2 + 1] = s1 + bb[1];
    }
}

// ---------------- fused CRF: 96 blocks, role = fwd / bwd / viterbi ----------------
__global__ void k_crf(float* out, int out_size) {
    __shared__ float sT[Sv * Sv];
    __shared__ float aA[104];
    __shared__ float aB[104];
    __shared__ float red[4];
    int role = blockIdx.x >> 5;
    int b = blockIdx.x & 31;
    int tid = threadIdx.x;  // 128
    const float* src = (role == 2) ? g_T : g_expT;
    for (int i = tid; i < Sv * Sv; i += 128) sT[i] = src[i];
    if (tid < 104) { aA[tid] = -INFINITY; aB[tid] = -INFINITY; }
    __syncthreads();
    const float* E = g_emis2 + b * 2048;

    if (role == 0) {
        // ---- forward ----
        if (tid < Sv) {
            float a0 = g_start[tid] + (tid == 0 ? E[0] : E[1]);
            aA[tid] = a0;
            g_alphas[b * Sv + tid] = a0;
        }
        __syncthreads();
        for (int t = 1; t < Lv; t++) {
            float v = (tid < Sv) ? aA[tid] : -INFINITY;
            float m = blkMax128(v, red);
            if (tid < Sv) aB[tid] = __expf(aA[tid] - m);
            __syncthreads();
            float e0 = E[t * 2], e1 = E[t * 2 + 1];
            float anew = -INFINITY;
            if (tid < Sv) {
                float s = 0.f;
                #pragma unroll 4
                for (int i = 0; i < Sv; i++) s += aB[i] * sT[i * Sv + tid];
                anew = m + logf(s) + (tid == 0 ? e0 : e1);
                g_alphas[(t * Bv + b) * Sv + tid] = anew;
            }
            __syncthreads();
            if (tid < Sv) aA[tid] = anew;
            __syncthreads();
        }
        float v = (tid < Sv) ? aA[tid] + g_end[tid] : -INFINITY;
        float m = blkMax128(v, red);
        float s = blkSum128((tid < Sv) ? __expf(v - m) : 0.f, red);
        if (tid == 0) g_logZ[b] = m + logf(s);
    } else if (role == 1) {
        // ---- backward ----
        if (tid < Sv) {
            aA[tid] = g_end[tid];
            g_betas[(1023 * Bv + b) * Sv + tid] = aA[tid];
        }
        __syncthreads();
        for (int t = Lv - 2; t >= 0; t--) {
            float e0 = E[(t + 1) * 2], e1 = E[(t + 1) * 2 + 1];
            float q = (tid < Sv) ? aA[tid] + (tid == 0 ? e0 : e1) : -INFINITY;
            float m = blkMax128(q, red);
            if (tid < Sv) aB[tid] = __expf(q - m);
            __syncthreads();
            float bnew = -INFINITY;
            if (tid < Sv) {
                float s = 0.f;
                #pragma unroll 4
                for (int j = 0; j < Sv; j++) s += sT[tid * Sv + j] * aB[j];
                bnew = m + logf(s);
                g_betas[(t * Bv + b) * Sv + tid] = bnew;
            }
            __syncthreads();
            if (tid < Sv) aA[tid] = bnew;
            __syncthreads();
        }
    } else {
        // ---- viterbi ----
        if (tid < Sv) aA[tid] = g_start[tid] + (tid == 0 ? E[0] : E[1]);
        __syncthreads();
        float* cur = aA;
        float* nxt = aB;
        unsigned char* P = g_ptr + b * (Lv - 1) * Sv;
        for (int t = 1; t < Lv; t++) {
            float e0 = E[t * 2], e1 = E[t * 2 + 1];
            if (tid < Sv) {
                float best = -INFINITY;
                int bi = 0;
                #pragma unroll 4
                for (int i = 0; i < Sv; i++) {
                    float sc = cur[i] + sT[i * Sv + tid];
                    if (sc > best) { best = sc; bi = i; }
                }
                nxt[tid] = best + (tid == 0 ? e0 : e1);
                P[(t - 1) * Sv + tid] = (unsigned char)bi;
            }
            __syncthreads();
            float* tmp = cur; cur = nxt; nxt = tmp;
        }
        if (tid == 0 && out_size >= Bv * Lv * Sv + Bv * Lv) {
            float best = -INFINITY;
            int last = 0;
            for (int j = 0; j < Sv; j++) {
                float f = cur[j] + g_end[j];
                if (f > best) { best = f; last = j; }
            }
            g_best[b] = best;
            float* paths = out + Bv * Lv * Sv;
            int st = last;
            paths[b * Lv + Lv - 1] = (float)st;
            for (int t = Lv - 1; t >= 1; t--) {
                st = P[(t - 1) * Sv + st];
                paths[b * Lv + t - 1] = (float)st;
            }
        }
    }
}

// ---------------- marginals + path probs ----------------
__global__ void k_marg(float* out, int out_size) {
    __shared__ float red[4];
    int bl = blockIdx.x;  // = b*1024 + l
    int b = bl >> 10, l = bl & 1023;
    int tid = threadIdx.x;
    int base = (l * Bv + b) * Sv;
    float v = (tid < Sv) ? g_alphas[base + tid] + g_betas[base + tid] : -INFINITY;
    float m = blkMax128(v, red);
    float e = (tid < Sv) ? __expf(v - m) : 0.f;
    float s = blkSum128(e, red);
    if (tid < Sv) out[bl * Sv + tid] = e / s;
    if (bl == 0 && tid < Bv && out_size >= Bv * Lv * Sv + Bv * Lv + Bv)
        out[Bv * Lv * Sv + Bv * Lv + tid] = __expf(g_best[tid] - g_logZ[tid]);
}

extern "C" void kernel_launch(void* const* d_in, const int* in_sizes, int n_in,
                              void* d_out, int out_size) {
    // Locate W_bneck by its unique size; weights follow in dict order.
    int iW = 3;
    for (int i = 0; i < n_in; i++)
        if (in_sizes[i] == Dv * Cv) { iW = i; break; }
    const float* emb     = (const float*)d_in[0];
    const float* W_bneck = (const float*)d_in[iW];
    const float* b_bneck = (const float*)d_in[iW + 1];
    const float* ln_g    = (const float*)d_in[iW + 2];
    const float* ln_b    = (const float*)d_in[iW + 3];
    const float* conv1_w = (const float*)d_in[iW + 4];
    const float* conv1_b = (const float*)d_in[iW + 5];
    const float* Wih_f   = (const float*)d_in[iW + 6];
    const float* Whh_f   = (const float*)d_in[iW + 7];
    const float* bih_f   = (const float*)d_in[iW + 8];
    const float* bhh_f   = (const float*)d_in[iW + 9];
    const float* Wih_b   = (const float*)d_in[iW + 10];
    const float* Whh_b   = (const float*)d_in[iW + 11];
    const float* bih_b   = (const float*)d_in[iW + 12];
    const float* bhh_b   = (const float*)d_in[iW + 13];
    const float* conv2_w = (const float*)d_in[iW + 14];
    const float* conv2_b = (const float*)d_in[iW + 15];
    const float* W_emis  = (const float*)d_in[iW + 16];
    const float* b_emis  = (const float*)d_in[iW + 17];
    const float* crf_t   = (const float*)d_in[iW + 18];
    const float* crf_s   = (const float*)d_in[iW + 19];
    const float* crf_e   = (const float*)d_in[iW + 20];
    float* out = (float*)d_out;

    k_pos<<<Dv, 128>>>();
    k_setup<<<128, 256>>>(crf_t, crf_s, crf_e, Whh_f, Whh_b, bih_f, bhh_f, bih_b, bhh_b);
    k_gemm1<<<dim3(512, 4), 256>>>(emb, W_bneck, b_bneck);
    k_ln<<<Bv * Lv, 128>>>(ln_g, ln_b);
    k_conv1<<<512, 256>>>(conv1_w, conv1_b);
    k_xproj<<<dim3(512, 8, 2), 256>>>(Wih_f, Wih_b);
    k_lstm<<<32, 256>>>();
    k_conv2<<<dim3(512, 2), 256>>>(conv2_w, conv2_b);
    k_emis<<<Bv * Lv, 128>>>(W_emis, b_emis);
    k_crf<<<96, 128>>>(out, out_size);
    k_marg<<<Bv * Lv, 128>>>(out, out_size);
}